// round 2
// baseline (speedup 1.0000x reference)
#include <cuda_runtime.h>

// ---------------------------------------------------------------------------
// LSTM forecaster: 2-layer encoder (T=20, F=10, H=128) -> 2-layer decoder
// (T_FUT=30, autoregressive on 2-dim head output). Batch rows independent ->
// each CTA owns 32 rows and runs the whole recurrence locally.
//
// Thread map: 512 threads = 128 hidden-j  x  4 row-groups (8 rows each).
// Thread (j, rg) computes gates i/f/g/o for hidden unit j across its 8 rows.
// Cell state c lives in registers; h lives in smem (broadcast reads).
// Weights are staged gmem->smem in 32-column chunks, conflict-free layout.
// Inner product accumulated with packed fma.rn.f32x2 (even/odd k lanes).
// ---------------------------------------------------------------------------

#define THREADS 512
#define HID     128
#define NG      4
#define GATES   512      // 4*HID
#define ROWS    32       // batch rows per CTA
#define RPT     8        // rows per thread
#define KC      32       // staged K-chunk columns
#define WPAD    36       // smem row stride for staged weights (floats)
#define HSTR    132      // smem row stride for h (floats)
#define XPAD    13       // smem row stride for x / Wih0 (floats)
#define T_HIST  20
#define T_FUT   30
#define FIN     10

#define SMEM_FLOATS 37860
#define SMEM_BYTES  (SMEM_FLOATS * 4)

__device__ __forceinline__ void fma2(unsigned long long &acc,
                                     unsigned long long a,
                                     unsigned long long b) {
    asm("fma.rn.f32x2 %0, %1, %2, %0;" : "+l"(acc) : "l"(a), "l"(b));
}
__device__ __forceinline__ unsigned long long pack2(float lo, float hi) {
    unsigned long long v;
    asm("mov.b64 %0, {%1, %2};" : "=l"(v)
        : "r"(__float_as_uint(lo)), "r"(__float_as_uint(hi)));
    return v;
}
__device__ __forceinline__ float sum2(unsigned long long v) {
    unsigned int l, h;
    asm("mov.b64 {%0, %1}, %2;" : "=r"(l), "=r"(h) : "l"(v));
    return __uint_as_float(l) + __uint_as_float(h);
}
__device__ __forceinline__ float sigf(float x) {
    return __fdividef(1.0f, 1.0f + __expf(-x));
}
__device__ __forceinline__ float tanhf_fast(float x) {
    // 1 - 2/(exp(2x)+1); saturates correctly at +/-inf of exp
    return 1.0f - __fdividef(2.0f, __expf(2.0f * x) + 1.0f);
}

__global__ void __launch_bounds__(THREADS, 1)
lstm_forecaster_kernel(const float* __restrict__ hist,
                       const float* __restrict__ eWih0, const float* __restrict__ eWhh0,
                       const float* __restrict__ ebih0, const float* __restrict__ ebhh0,
                       const float* __restrict__ eWih1, const float* __restrict__ eWhh1,
                       const float* __restrict__ ebih1, const float* __restrict__ ebhh1,
                       const float* __restrict__ dWih0, const float* __restrict__ dWhh0,
                       const float* __restrict__ dbih0, const float* __restrict__ dbhh0,
                       const float* __restrict__ dWih1, const float* __restrict__ dWhh1,
                       const float* __restrict__ dbih1, const float* __restrict__ dbhh1,
                       const float* __restrict__ headW, const float* __restrict__ headb,
                       float* __restrict__ out)
{
    extern __shared__ float sm[];
    float* W_sm     = sm;                          // 512*36 = 18432
    float* Wih0_sm  = W_sm     + GATES * WPAD;     // 512*13 =  6656
    float* dWih0_sm = Wih0_sm  + GATES * XPAD;     // 512*3  =  1536
    float* b_e0     = dWih0_sm + GATES * 3;        // 512
    float* b_e1     = b_e0 + GATES;                // 512
    float* b_d0     = b_e1 + GATES;                // 512
    float* b_d1     = b_d0 + GATES;                // 512
    float* headW_sm = b_d1 + GATES;                // 256
    float* headb_sm = headW_sm + 256;              // 4 (2 used)
    float* h0_sm    = headb_sm + 4;                // 32*132 = 4224
    float* h1_sm    = h0_sm + ROWS * HSTR;         // 4224
    float* x_sm     = h1_sm + ROWS * HSTR;         // 32*13 = 416
    float* y_sm     = x_sm + ROWS * XPAD;          // 64

    const int tid = threadIdx.x;
    const int j   = tid & (HID - 1);
    const int rg  = tid >> 7;
    const int r0  = rg * RPT;
    const int brow = blockIdx.x * ROWS;

    // ---- persistent preload ----
    for (int i = tid; i < GATES * FIN; i += THREADS) {
        int row = i / FIN, f = i - row * FIN;
        Wih0_sm[row * XPAD + f] = eWih0[i];
    }
    for (int i = tid; i < GATES * 2; i += THREADS) {
        int row = i >> 1, d = i & 1;
        dWih0_sm[row * 3 + d] = dWih0[i];
    }
    {
        int i = tid;  // THREADS == GATES
        b_e0[i] = ebih0[i] + ebhh0[i];
        b_e1[i] = ebih1[i] + ebhh1[i];
        b_d0[i] = dbih0[i] + dbhh0[i];
        b_d1[i] = dbih1[i] + dbhh1[i];
    }
    if (tid < 256) headW_sm[tid] = headW[tid];
    if (tid < 2)   headb_sm[tid] = headb[tid];
    for (int i = tid; i < ROWS * HSTR; i += THREADS) { h0_sm[i] = 0.0f; h1_sm[i] = 0.0f; }
    if (tid < ROWS * 2) y_sm[tid] = 0.0f;
    __syncthreads();

    float c0[RPT], c1[RPT];
#pragma unroll
    for (int r = 0; r < RPT; ++r) { c0[r] = 0.0f; c1[r] = 0.0f; }

    unsigned long long acc2[NG][RPT];

    // stage one KC-column chunk of a (512 x 128) weight matrix, then accumulate
    auto run_matrix = [&](const float* __restrict__ Wg, const float* __restrict__ hsm) {
#pragma unroll 1
        for (int k0 = 0; k0 < HID; k0 += KC) {
            __syncthreads();
#pragma unroll
            for (int i = tid; i < GATES * (KC / 4); i += THREADS) {   // 8 iters
                int row = i >> 3, kk = (i & 7) << 2;
                *(float4*)(W_sm + row * WPAD + kk) =
                    *(const float4*)(Wg + row * HID + k0 + kk);
            }
            __syncthreads();
#pragma unroll 4
            for (int kk = 0; kk < KC; kk += 4) {
                ulonglong2 w[NG];
#pragma unroll
                for (int g = 0; g < NG; ++g)
                    w[g] = *(const ulonglong2*)(W_sm + (g * HID + j) * WPAD + kk);
#pragma unroll
                for (int r = 0; r < RPT; ++r) {
                    ulonglong2 hd = *(const ulonglong2*)(hsm + (r0 + r) * HSTR + k0 + kk);
#pragma unroll
                    for (int g = 0; g < NG; ++g) {
                        fma2(acc2[g][r], w[g].x, hd.x);
                        fma2(acc2[g][r], w[g].y, hd.y);
                    }
                }
            }
        }
    };

    auto init_bias = [&](const float* __restrict__ bsm) {
#pragma unroll
        for (int g = 0; g < NG; ++g) {
            float bg = bsm[g * HID + j];
#pragma unroll
            for (int r = 0; r < RPT; ++r) acc2[g][r] = pack2(bg, 0.0f);
        }
    };

    auto finish_layer = [&](float (&c)[RPT], float* __restrict__ hsm_out) {
        float hn[RPT];
#pragma unroll
        for (int r = 0; r < RPT; ++r) {
            float gi = sigf(sum2(acc2[0][r]));
            float gf = sigf(sum2(acc2[1][r]));
            float gg = tanhf_fast(sum2(acc2[2][r]));
            float go = sigf(sum2(acc2[3][r]));
            float cn = gf * c[r] + gi * gg;
            c[r] = cn;
            hn[r] = go * tanhf_fast(cn);
        }
        __syncthreads();   // all reads of old h done before overwrite
#pragma unroll
        for (int r = 0; r < RPT; ++r) hsm_out[(r0 + r) * HSTR + j] = hn[r];
    };

    // ================= encoder =================
#pragma unroll 1
    for (int t = 0; t < T_HIST; ++t) {
        // load x tile (32 rows x 10 features)
        if (tid < ROWS * FIN) {
            int r = tid / FIN, f = tid - r * FIN;
            x_sm[r * XPAD + f] =
                hist[(size_t)(brow + r) * (T_HIST * FIN) + t * FIN + f];
        }
        __syncthreads();

        // --- layer 0: bias + x-part in fp32, then pack ---
        {
            float a[NG][RPT];
#pragma unroll
            for (int g = 0; g < NG; ++g) {
                float bg = b_e0[g * HID + j];
#pragma unroll
                for (int r = 0; r < RPT; ++r) a[g][r] = bg;
            }
#pragma unroll
            for (int f = 0; f < FIN; ++f) {
                float wg[NG];
#pragma unroll
                for (int g = 0; g < NG; ++g)
                    wg[g] = Wih0_sm[(g * HID + j) * XPAD + f];
#pragma unroll
                for (int r = 0; r < RPT; ++r) {
                    float xv = x_sm[(r0 + r) * XPAD + f];
#pragma unroll
                    for (int g = 0; g < NG; ++g) a[g][r] += wg[g] * xv;
                }
            }
#pragma unroll
            for (int g = 0; g < NG; ++g)
#pragma unroll
                for (int r = 0; r < RPT; ++r) acc2[g][r] = pack2(a[g][r], 0.0f);
        }
        run_matrix(eWhh0, h0_sm);
        finish_layer(c0, h0_sm);

        // --- layer 1 ---
        init_bias(b_e1);
        run_matrix(eWih1, h0_sm);   // input = new h0
        run_matrix(eWhh1, h1_sm);   // recurrent = old h1
        finish_layer(c1, h1_sm);
    }

    // ================= decoder =================
#pragma unroll 1
    for (int t = 0; t < T_FUT; ++t) {
        // --- layer 0: bias + y-part (2 dims) ---
        {
            float a[NG][RPT];
#pragma unroll
            for (int g = 0; g < NG; ++g) {
                float bg = b_d0[g * HID + j];
#pragma unroll
                for (int r = 0; r < RPT; ++r) a[g][r] = bg;
            }
#pragma unroll
            for (int d = 0; d < 2; ++d) {
                float wg[NG];
#pragma unroll
                for (int g = 0; g < NG; ++g)
                    wg[g] = dWih0_sm[(g * HID + j) * 3 + d];
#pragma unroll
                for (int r = 0; r < RPT; ++r) {
                    float yv = y_sm[(r0 + r) * 2 + d];
#pragma unroll
                    for (int g = 0; g < NG; ++g) a[g][r] += wg[g] * yv;
                }
            }
#pragma unroll
            for (int g = 0; g < NG; ++g)
#pragma unroll
                for (int r = 0; r < RPT; ++r) acc2[g][r] = pack2(a[g][r], 0.0f);
        }
        run_matrix(dWhh0, h0_sm);
        finish_layer(c0, h0_sm);

        // --- layer 1 ---
        init_bias(b_d1);
        run_matrix(dWih1, h0_sm);
        run_matrix(dWhh1, h1_sm);
        finish_layer(c1, h1_sm);
        __syncthreads();   // h1 stores visible before head reads

        // --- head: dxy = h1 @ headW^T + headb ---
        if (tid < ROWS * 2) {
            int r = tid >> 1, d = tid & 1;
            float s = headb_sm[d];
            const float* hw = headW_sm + d * HID;
            const float* hr = h1_sm + r * HSTR;
#pragma unroll 8
            for (int jj = 0; jj < HID; ++jj) s += hr[jj] * hw[jj];
            y_sm[r * 2 + d] = s;
            out[(size_t)(brow + r) * (T_FUT * 2) + t * 2 + d] = s;
        }
        __syncthreads();   // y_sm visible before next step's y-part
    }
}

extern "C" void kernel_launch(void* const* d_in, const int* in_sizes, int n_in,
                              void* d_out, int out_size)
{
    const float* hist  = (const float*)d_in[0];
    const float* eWih0 = (const float*)d_in[1];
    const float* eWhh0 = (const float*)d_in[2];
    const float* ebih0 = (const float*)d_in[3];
    const float* ebhh0 = (const float*)d_in[4];
    const float* eWih1 = (const float*)d_in[5];
    const float* eWhh1 = (const float*)d_in[6];
    const float* ebih1 = (const float*)d_in[7];
    const float* ebhh1 = (const float*)d_in[8];
    const float* dWih0 = (const float*)d_in[9];
    const float* dWhh0 = (const float*)d_in[10];
    const float* dbih0 = (const float*)d_in[11];
    const float* dbhh0 = (const float*)d_in[12];
    const float* dWih1 = (const float*)d_in[13];
    const float* dWhh1 = (const float*)d_in[14];
    const float* dbih1 = (const float*)d_in[15];
    const float* dbhh1 = (const float*)d_in[16];
    const float* headW = (const float*)d_in[17];
    const float* headb = (const float*)d_in[18];
    // d_in[19] = fut_len (always 30 for this problem)

    int B = in_sizes[0] / (T_HIST * FIN);
    int grid = B / ROWS;

    cudaFuncSetAttribute(lstm_forecaster_kernel,
                         cudaFuncAttributeMaxDynamicSharedMemorySize, SMEM_BYTES);

    lstm_forecaster_kernel<<<grid, THREADS, SMEM_BYTES>>>(
        hist, eWih0, eWhh0, ebih0, ebhh0, eWih1, eWhh1, ebih1, ebhh1,
        dWih0, dWhh0, dbih0, dbhh0, dWih1, dWhh1, dbih1, dbhh1,
        headW, headb, (float*)d_out);
}

// round 4
// speedup vs baseline: 1.0002x; 1.0002x over previous
#include <cuda_runtime.h>

// ---------------------------------------------------------------------------
// LSTM forecaster: 2-layer encoder (T=20, F=10, H=128) -> 2-layer decoder
// (T_FUT=30, autoregressive on 2-dim head output). Batch rows independent ->
// each CTA owns 32 rows and runs the whole recurrence locally.
//
// Thread map: 512 threads = 128 hidden-j  x  4 row-groups (8 rows each).
// Thread (j, rg) computes gates i/f/g/o for hidden unit j across its 8 rows.
// Cell state c lives in registers; h lives in smem (broadcast reads).
// Weights are staged gmem->smem in 32-column chunks, conflict-free layout.
// Inner product accumulated with packed fma.rn.f32x2 (even/odd k lanes).
// ---------------------------------------------------------------------------

#define THREADS 512
#define HID     128
#define NG      4
#define GATES   512      // 4*HID
#define ROWS    32       // batch rows per CTA
#define RPT     8        // rows per thread
#define KC      32       // staged K-chunk columns
#define WPAD    36       // smem row stride for staged weights (floats)
#define HSTR    132      // smem row stride for h (floats)
#define XPAD    13       // smem row stride for x / Wih0 (floats)
#define T_HIST  20
#define T_FUT   30
#define FIN     10

#define SMEM_FLOATS 37860
#define SMEM_BYTES  (SMEM_FLOATS * 4)

__device__ __forceinline__ void fma2(unsigned long long &acc,
                                     unsigned long long a,
                                     unsigned long long b) {
    asm("fma.rn.f32x2 %0, %1, %2, %0;" : "+l"(acc) : "l"(a), "l"(b));
}
__device__ __forceinline__ unsigned long long pack2(float lo, float hi) {
    unsigned long long v;
    asm("mov.b64 %0, {%1, %2};" : "=l"(v)
        : "r"(__float_as_uint(lo)), "r"(__float_as_uint(hi)));
    return v;
}
__device__ __forceinline__ float sum2(unsigned long long v) {
    unsigned int l, h;
    asm("mov.b64 {%0, %1}, %2;" : "=r"(l), "=r"(h) : "l"(v));
    return __uint_as_float(l) + __uint_as_float(h);
}
__device__ __forceinline__ float sigf(float x) {
    return __fdividef(1.0f, 1.0f + __expf(-x));
}
__device__ __forceinline__ float tanhf_fast(float x) {
    // 1 - 2/(exp(2x)+1); saturates correctly at +/-inf of exp
    return 1.0f - __fdividef(2.0f, __expf(2.0f * x) + 1.0f);
}

__global__ void __launch_bounds__(THREADS, 1)
lstm_forecaster_kernel(const float* __restrict__ hist,
                       const float* __restrict__ eWih0, const float* __restrict__ eWhh0,
                       const float* __restrict__ ebih0, const float* __restrict__ ebhh0,
                       const float* __restrict__ eWih1, const float* __restrict__ eWhh1,
                       const float* __restrict__ ebih1, const float* __restrict__ ebhh1,
                       const float* __restrict__ dWih0, const float* __restrict__ dWhh0,
                       const float* __restrict__ dbih0, const float* __restrict__ dbhh0,
                       const float* __restrict__ dWih1, const float* __restrict__ dWhh1,
                       const float* __restrict__ dbih1, const float* __restrict__ dbhh1,
                       const float* __restrict__ headW, const float* __restrict__ headb,
                       float* __restrict__ out)
{
    extern __shared__ float sm[];
    float* W_sm     = sm;                          // 512*36 = 18432
    float* Wih0_sm  = W_sm     + GATES * WPAD;     // 512*13 =  6656
    float* dWih0_sm = Wih0_sm  + GATES * XPAD;     // 512*3  =  1536
    float* b_e0     = dWih0_sm + GATES * 3;        // 512
    float* b_e1     = b_e0 + GATES;                // 512
    float* b_d0     = b_e1 + GATES;                // 512
    float* b_d1     = b_d0 + GATES;                // 512
    float* headW_sm = b_d1 + GATES;                // 256
    float* headb_sm = headW_sm + 256;              // 4 (2 used)
    float* h0_sm    = headb_sm + 4;                // 32*132 = 4224
    float* h1_sm    = h0_sm + ROWS * HSTR;         // 4224
    float* x_sm     = h1_sm + ROWS * HSTR;         // 32*13 = 416
    float* y_sm     = x_sm + ROWS * XPAD;          // 64

    const int tid = threadIdx.x;
    const int j   = tid & (HID - 1);
    const int rg  = tid >> 7;
    const int r0  = rg * RPT;
    const int brow = blockIdx.x * ROWS;

    // ---- persistent preload ----
    for (int i = tid; i < GATES * FIN; i += THREADS) {
        int row = i / FIN, f = i - row * FIN;
        Wih0_sm[row * XPAD + f] = eWih0[i];
    }
    for (int i = tid; i < GATES * 2; i += THREADS) {
        int row = i >> 1, d = i & 1;
        dWih0_sm[row * 3 + d] = dWih0[i];
    }
    {
        int i = tid;  // THREADS == GATES
        b_e0[i] = ebih0[i] + ebhh0[i];
        b_e1[i] = ebih1[i] + ebhh1[i];
        b_d0[i] = dbih0[i] + dbhh0[i];
        b_d1[i] = dbih1[i] + dbhh1[i];
    }
    if (tid < 256) headW_sm[tid] = headW[tid];
    if (tid < 2)   headb_sm[tid] = headb[tid];
    for (int i = tid; i < ROWS * HSTR; i += THREADS) { h0_sm[i] = 0.0f; h1_sm[i] = 0.0f; }
    if (tid < ROWS * 2) y_sm[tid] = 0.0f;
    __syncthreads();

    float c0[RPT], c1[RPT];
#pragma unroll
    for (int r = 0; r < RPT; ++r) { c0[r] = 0.0f; c1[r] = 0.0f; }

    unsigned long long acc2[NG][RPT];

    // stage one KC-column chunk of a (512 x 128) weight matrix, then accumulate
    auto run_matrix = [&](const float* __restrict__ Wg, const float* __restrict__ hsm) {
#pragma unroll 1
        for (int k0 = 0; k0 < HID; k0 += KC) {
            __syncthreads();
#pragma unroll
            for (int i = tid; i < GATES * (KC / 4); i += THREADS) {   // 8 iters
                int row = i >> 3, kk = (i & 7) << 2;
                *(float4*)(W_sm + row * WPAD + kk) =
                    *(const float4*)(Wg + row * HID + k0 + kk);
            }
            __syncthreads();
#pragma unroll 4
            for (int kk = 0; kk < KC; kk += 4) {
                ulonglong2 w[NG];
#pragma unroll
                for (int g = 0; g < NG; ++g)
                    w[g] = *(const ulonglong2*)(W_sm + (g * HID + j) * WPAD + kk);
#pragma unroll
                for (int r = 0; r < RPT; ++r) {
                    ulonglong2 hd = *(const ulonglong2*)(hsm + (r0 + r) * HSTR + k0 + kk);
#pragma unroll
                    for (int g = 0; g < NG; ++g) {
                        fma2(acc2[g][r], w[g].x, hd.x);
                        fma2(acc2[g][r], w[g].y, hd.y);
                    }
                }
            }
        }
    };

    auto init_bias = [&](const float* __restrict__ bsm) {
#pragma unroll
        for (int g = 0; g < NG; ++g) {
            float bg = bsm[g * HID + j];
#pragma unroll
            for (int r = 0; r < RPT; ++r) acc2[g][r] = pack2(bg, 0.0f);
        }
    };

    auto finish_layer = [&](float (&c)[RPT], float* __restrict__ hsm_out) {
        float hn[RPT];
#pragma unroll
        for (int r = 0; r < RPT; ++r) {
            float gi = sigf(sum2(acc2[0][r]));
            float gf = sigf(sum2(acc2[1][r]));
            float gg = tanhf_fast(sum2(acc2[2][r]));
            float go = sigf(sum2(acc2[3][r]));
            float cn = gf * c[r] + gi * gg;
            c[r] = cn;
            hn[r] = go * tanhf_fast(cn);
        }
        __syncthreads();   // all reads of old h done before overwrite
#pragma unroll
        for (int r = 0; r < RPT; ++r) hsm_out[(r0 + r) * HSTR + j] = hn[r];
    };

    // ================= encoder =================
#pragma unroll 1
    for (int t = 0; t < T_HIST; ++t) {
        // load x tile (32 rows x 10 features)
        if (tid < ROWS * FIN) {
            int r = tid / FIN, f = tid - r * FIN;
            x_sm[r * XPAD + f] =
                hist[(size_t)(brow + r) * (T_HIST * FIN) + t * FIN + f];
        }
        __syncthreads();

        // --- layer 0: bias + x-part in fp32, then pack ---
        {
            float a[NG][RPT];
#pragma unroll
            for (int g = 0; g < NG; ++g) {
                float bg = b_e0[g * HID + j];
#pragma unroll
                for (int r = 0; r < RPT; ++r) a[g][r] = bg;
            }
#pragma unroll
            for (int f = 0; f < FIN; ++f) {
                float wg[NG];
#pragma unroll
                for (int g = 0; g < NG; ++g)
                    wg[g] = Wih0_sm[(g * HID + j) * XPAD + f];
#pragma unroll
                for (int r = 0; r < RPT; ++r) {
                    float xv = x_sm[(r0 + r) * XPAD + f];
#pragma unroll
                    for (int g = 0; g < NG; ++g) a[g][r] += wg[g] * xv;
                }
            }
#pragma unroll
            for (int g = 0; g < NG; ++g)
#pragma unroll
                for (int r = 0; r < RPT; ++r) acc2[g][r] = pack2(a[g][r], 0.0f);
        }
        run_matrix(eWhh0, h0_sm);
        finish_layer(c0, h0_sm);

        // --- layer 1 ---
        init_bias(b_e1);
        run_matrix(eWih1, h0_sm);   // input = new h0
        run_matrix(eWhh1, h1_sm);   // recurrent = old h1
        finish_layer(c1, h1_sm);
    }

    // ================= decoder =================
#pragma unroll 1
    for (int t = 0; t < T_FUT; ++t) {
        // --- layer 0: bias + y-part (2 dims) ---
        {
            float a[NG][RPT];
#pragma unroll
            for (int g = 0; g < NG; ++g) {
                float bg = b_d0[g * HID + j];
#pragma unroll
                for (int r = 0; r < RPT; ++r) a[g][r] = bg;
            }
#pragma unroll
            for (int d = 0; d < 2; ++d) {
                float wg[NG];
#pragma unroll
                for (int g = 0; g < NG; ++g)
                    wg[g] = dWih0_sm[(g * HID + j) * 3 + d];
#pragma unroll
                for (int r = 0; r < RPT; ++r) {
                    float yv = y_sm[(r0 + r) * 2 + d];
#pragma unroll
                    for (int g = 0; g < NG; ++g) a[g][r] += wg[g] * yv;
                }
            }
#pragma unroll
            for (int g = 0; g < NG; ++g)
#pragma unroll
                for (int r = 0; r < RPT; ++r) acc2[g][r] = pack2(a[g][r], 0.0f);
        }
        run_matrix(dWhh0, h0_sm);
        finish_layer(c0, h0_sm);

        // --- layer 1 ---
        init_bias(b_d1);
        run_matrix(dWih1, h0_sm);
        run_matrix(dWhh1, h1_sm);
        finish_layer(c1, h1_sm);
        __syncthreads();   // h1 stores visible before head reads

        // --- head: dxy = h1 @ headW^T + headb ---
        if (tid < ROWS * 2) {
            int r = tid >> 1, d = tid & 1;
            float s = headb_sm[d];
            const float* hw = headW_sm + d * HID;
            const float* hr = h1_sm + r * HSTR;
#pragma unroll 8
            for (int jj = 0; jj < HID; ++jj) s += hr[jj] * hw[jj];
            y_sm[r * 2 + d] = s;
            out[(size_t)(brow + r) * (T_FUT * 2) + t * 2 + d] = s;
        }
        __syncthreads();   // y_sm visible before next step's y-part
    }
}

extern "C" void kernel_launch(void* const* d_in, const int* in_sizes, int n_in,
                              void* d_out, int out_size)
{
    const float* hist  = (const float*)d_in[0];
    const float* eWih0 = (const float*)d_in[1];
    const float* eWhh0 = (const float*)d_in[2];
    const float* ebih0 = (const float*)d_in[3];
    const float* ebhh0 = (const float*)d_in[4];
    const float* eWih1 = (const float*)d_in[5];
    const float* eWhh1 = (const float*)d_in[6];
    const float* ebih1 = (const float*)d_in[7];
    const float* ebhh1 = (const float*)d_in[8];
    const float* dWih0 = (const float*)d_in[9];
    const float* dWhh0 = (const float*)d_in[10];
    const float* dbih0 = (const float*)d_in[11];
    const float* dbhh0 = (const float*)d_in[12];
    const float* dWih1 = (const float*)d_in[13];
    const float* dWhh1 = (const float*)d_in[14];
    const float* dbih1 = (const float*)d_in[15];
    const float* dbhh1 = (const float*)d_in[16];
    const float* headW = (const float*)d_in[17];
    const float* headb = (const float*)d_in[18];
    // d_in[19] = fut_len (always 30 for this problem)

    int B = in_sizes[0] / (T_HIST * FIN);
    int grid = B / ROWS;

    cudaFuncSetAttribute(lstm_forecaster_kernel,
                         cudaFuncAttributeMaxDynamicSharedMemorySize, SMEM_BYTES);

    lstm_forecaster_kernel<<<grid, THREADS, SMEM_BYTES>>>(
        hist, eWih0, eWhh0, ebih0, ebhh0, eWih1, eWhh1, ebih1, ebhh1,
        dWih0, dWhh0, dbih0, dbhh0, dWih1, dWhh1, dbih1, dbhh1,
        headW, headb, (float*)d_out);
}

// round 5
// speedup vs baseline: 1.0008x; 1.0006x over previous
#include <cuda_runtime.h>

// ---------------------------------------------------------------------------
// LSTM forecaster: 2-layer encoder (T=20, F=10, H=128) -> 2-layer decoder
// (T_FUT=30, autoregressive on 2-dim head output). Batch rows independent ->
// each CTA owns 32 rows and runs the whole recurrence locally.
//
// Thread map: 512 threads = 128 hidden-j  x  4 row-groups (8 rows each).
// Thread (j, rg) computes gates i/f/g/o for hidden unit j across its 8 rows.
// Cell state c lives in registers; h lives in smem (broadcast reads).
// Weights are staged gmem->smem in 32-column chunks, conflict-free layout.
// Inner product accumulated with packed fma.rn.f32x2 (even/odd k lanes).
// ---------------------------------------------------------------------------

#define THREADS 512
#define HID     128
#define NG      4
#define GATES   512      // 4*HID
#define ROWS    32       // batch rows per CTA
#define RPT     8        // rows per thread
#define KC      32       // staged K-chunk columns
#define WPAD    36       // smem row stride for staged weights (floats)
#define HSTR    132      // smem row stride for h (floats)
#define XPAD    13       // smem row stride for x / Wih0 (floats)
#define T_HIST  20
#define T_FUT   30
#define FIN     10

#define SMEM_FLOATS 37860
#define SMEM_BYTES  (SMEM_FLOATS * 4)

__device__ __forceinline__ void fma2(unsigned long long &acc,
                                     unsigned long long a,
                                     unsigned long long b) {
    asm("fma.rn.f32x2 %0, %1, %2, %0;" : "+l"(acc) : "l"(a), "l"(b));
}
__device__ __forceinline__ unsigned long long pack2(float lo, float hi) {
    unsigned long long v;
    asm("mov.b64 %0, {%1, %2};" : "=l"(v)
        : "r"(__float_as_uint(lo)), "r"(__float_as_uint(hi)));
    return v;
}
__device__ __forceinline__ float sum2(unsigned long long v) {
    unsigned int l, h;
    asm("mov.b64 {%0, %1}, %2;" : "=r"(l), "=r"(h) : "l"(v));
    return __uint_as_float(l) + __uint_as_float(h);
}
__device__ __forceinline__ float sigf(float x) {
    return __fdividef(1.0f, 1.0f + __expf(-x));
}
__device__ __forceinline__ float tanhf_fast(float x) {
    // 1 - 2/(exp(2x)+1); saturates correctly at +/-inf of exp
    return 1.0f - __fdividef(2.0f, __expf(2.0f * x) + 1.0f);
}

__global__ void __launch_bounds__(THREADS, 1)
lstm_forecaster_kernel(const float* __restrict__ hist,
                       const float* __restrict__ eWih0, const float* __restrict__ eWhh0,
                       const float* __restrict__ ebih0, const float* __restrict__ ebhh0,
                       const float* __restrict__ eWih1, const float* __restrict__ eWhh1,
                       const float* __restrict__ ebih1, const float* __restrict__ ebhh1,
                       const float* __restrict__ dWih0, const float* __restrict__ dWhh0,
                       const float* __restrict__ dbih0, const float* __restrict__ dbhh0,
                       const float* __restrict__ dWih1, const float* __restrict__ dWhh1,
                       const float* __restrict__ dbih1, const float* __restrict__ dbhh1,
                       const float* __restrict__ headW, const float* __restrict__ headb,
                       float* __restrict__ out)
{
    extern __shared__ float sm[];
    float* W_sm     = sm;                          // 512*36 = 18432
    float* Wih0_sm  = W_sm     + GATES * WPAD;     // 512*13 =  6656
    float* dWih0_sm = Wih0_sm  + GATES * XPAD;     // 512*3  =  1536
    float* b_e0     = dWih0_sm + GATES * 3;        // 512
    float* b_e1     = b_e0 + GATES;                // 512
    float* b_d0     = b_e1 + GATES;                // 512
    float* b_d1     = b_d0 + GATES;                // 512
    float* headW_sm = b_d1 + GATES;                // 256
    float* headb_sm = headW_sm + 256;              // 4 (2 used)
    float* h0_sm    = headb_sm + 4;                // 32*132 = 4224
    float* h1_sm    = h0_sm + ROWS * HSTR;         // 4224
    float* x_sm     = h1_sm + ROWS * HSTR;         // 32*13 = 416
    float* y_sm     = x_sm + ROWS * XPAD;          // 64

    const int tid = threadIdx.x;
    const int j   = tid & (HID - 1);
    const int rg  = tid >> 7;
    const int r0  = rg * RPT;
    const int brow = blockIdx.x * ROWS;

    // ---- persistent preload ----
    for (int i = tid; i < GATES * FIN; i += THREADS) {
        int row = i / FIN, f = i - row * FIN;
        Wih0_sm[row * XPAD + f] = eWih0[i];
    }
    for (int i = tid; i < GATES * 2; i += THREADS) {
        int row = i >> 1, d = i & 1;
        dWih0_sm[row * 3 + d] = dWih0[i];
    }
    {
        int i = tid;  // THREADS == GATES
        b_e0[i] = ebih0[i] + ebhh0[i];
        b_e1[i] = ebih1[i] + ebhh1[i];
        b_d0[i] = dbih0[i] + dbhh0[i];
        b_d1[i] = dbih1[i] + dbhh1[i];
    }
    if (tid < 256) headW_sm[tid] = headW[tid];
    if (tid < 2)   headb_sm[tid] = headb[tid];
    for (int i = tid; i < ROWS * HSTR; i += THREADS) { h0_sm[i] = 0.0f; h1_sm[i] = 0.0f; }
    if (tid < ROWS * 2) y_sm[tid] = 0.0f;
    __syncthreads();

    float c0[RPT], c1[RPT];
#pragma unroll
    for (int r = 0; r < RPT; ++r) { c0[r] = 0.0f; c1[r] = 0.0f; }

    unsigned long long acc2[NG][RPT];

    // stage one KC-column chunk of a (512 x 128) weight matrix, then accumulate
    auto run_matrix = [&](const float* __restrict__ Wg, const float* __restrict__ hsm) {
#pragma unroll 1
        for (int k0 = 0; k0 < HID; k0 += KC) {
            __syncthreads();
#pragma unroll
            for (int i = tid; i < GATES * (KC / 4); i += THREADS) {   // 8 iters
                int row = i >> 3, kk = (i & 7) << 2;
                *(float4*)(W_sm + row * WPAD + kk) =
                    *(const float4*)(Wg + row * HID + k0 + kk);
            }
            __syncthreads();
#pragma unroll 4
            for (int kk = 0; kk < KC; kk += 4) {
                ulonglong2 w[NG];
#pragma unroll
                for (int g = 0; g < NG; ++g)
                    w[g] = *(const ulonglong2*)(W_sm + (g * HID + j) * WPAD + kk);
#pragma unroll
                for (int r = 0; r < RPT; ++r) {
                    ulonglong2 hd = *(const ulonglong2*)(hsm + (r0 + r) * HSTR + k0 + kk);
#pragma unroll
                    for (int g = 0; g < NG; ++g) {
                        fma2(acc2[g][r], w[g].x, hd.x);
                        fma2(acc2[g][r], w[g].y, hd.y);
                    }
                }
            }
        }
    };

    auto init_bias = [&](const float* __restrict__ bsm) {
#pragma unroll
        for (int g = 0; g < NG; ++g) {
            float bg = bsm[g * HID + j];
#pragma unroll
            for (int r = 0; r < RPT; ++r) acc2[g][r] = pack2(bg, 0.0f);
        }
    };

    auto finish_layer = [&](float (&c)[RPT], float* __restrict__ hsm_out) {
        float hn[RPT];
#pragma unroll
        for (int r = 0; r < RPT; ++r) {
            float gi = sigf(sum2(acc2[0][r]));
            float gf = sigf(sum2(acc2[1][r]));
            float gg = tanhf_fast(sum2(acc2[2][r]));
            float go = sigf(sum2(acc2[3][r]));
            float cn = gf * c[r] + gi * gg;
            c[r] = cn;
            hn[r] = go * tanhf_fast(cn);
        }
        __syncthreads();   // all reads of old h done before overwrite
#pragma unroll
        for (int r = 0; r < RPT; ++r) hsm_out[(r0 + r) * HSTR + j] = hn[r];
    };

    // ================= encoder =================
#pragma unroll 1
    for (int t = 0; t < T_HIST; ++t) {
        // load x tile (32 rows x 10 features)
        if (tid < ROWS * FIN) {
            int r = tid / FIN, f = tid - r * FIN;
            x_sm[r * XPAD + f] =
                hist[(size_t)(brow + r) * (T_HIST * FIN) + t * FIN + f];
        }
        __syncthreads();

        // --- layer 0: bias + x-part in fp32, then pack ---
        {
            float a[NG][RPT];
#pragma unroll
            for (int g = 0; g < NG; ++g) {
                float bg = b_e0[g * HID + j];
#pragma unroll
                for (int r = 0; r < RPT; ++r) a[g][r] = bg;
            }
#pragma unroll
            for (int f = 0; f < FIN; ++f) {
                float wg[NG];
#pragma unroll
                for (int g = 0; g < NG; ++g)
                    wg[g] = Wih0_sm[(g * HID + j) * XPAD + f];
#pragma unroll
                for (int r = 0; r < RPT; ++r) {
                    float xv = x_sm[(r0 + r) * XPAD + f];
#pragma unroll
                    for (int g = 0; g < NG; ++g) a[g][r] += wg[g] * xv;
                }
            }
#pragma unroll
            for (int g = 0; g < NG; ++g)
#pragma unroll
                for (int r = 0; r < RPT; ++r) acc2[g][r] = pack2(a[g][r], 0.0f);
        }
        run_matrix(eWhh0, h0_sm);
        finish_layer(c0, h0_sm);

        // --- layer 1 ---
        init_bias(b_e1);
        run_matrix(eWih1, h0_sm);   // input = new h0
        run_matrix(eWhh1, h1_sm);   // recurrent = old h1
        finish_layer(c1, h1_sm);
    }

    // ================= decoder =================
#pragma unroll 1
    for (int t = 0; t < T_FUT; ++t) {
        // --- layer 0: bias + y-part (2 dims) ---
        {
            float a[NG][RPT];
#pragma unroll
            for (int g = 0; g < NG; ++g) {
                float bg = b_d0[g * HID + j];
#pragma unroll
                for (int r = 0; r < RPT; ++r) a[g][r] = bg;
            }
#pragma unroll
            for (int d = 0; d < 2; ++d) {
                float wg[NG];
#pragma unroll
                for (int g = 0; g < NG; ++g)
                    wg[g] = dWih0_sm[(g * HID + j) * 3 + d];
#pragma unroll
                for (int r = 0; r < RPT; ++r) {
                    float yv = y_sm[(r0 + r) * 2 + d];
#pragma unroll
                    for (int g = 0; g < NG; ++g) a[g][r] += wg[g] * yv;
                }
            }
#pragma unroll
            for (int g = 0; g < NG; ++g)
#pragma unroll
                for (int r = 0; r < RPT; ++r) acc2[g][r] = pack2(a[g][r], 0.0f);
        }
        run_matrix(dWhh0, h0_sm);
        finish_layer(c0, h0_sm);

        // --- layer 1 ---
        init_bias(b_d1);
        run_matrix(dWih1, h0_sm);
        run_matrix(dWhh1, h1_sm);
        finish_layer(c1, h1_sm);
        __syncthreads();   // h1 stores visible before head reads

        // --- head: dxy = h1 @ headW^T + headb ---
        if (tid < ROWS * 2) {
            int r = tid >> 1, d = tid & 1;
            float s = headb_sm[d];
            const float* hw = headW_sm + d * HID;
            const float* hr = h1_sm + r * HSTR;
#pragma unroll 8
            for (int jj = 0; jj < HID; ++jj) s += hr[jj] * hw[jj];
            y_sm[r * 2 + d] = s;
            out[(size_t)(brow + r) * (T_FUT * 2) + t * 2 + d] = s;
        }
        __syncthreads();   // y_sm visible before next step's y-part
    }
}

extern "C" void kernel_launch(void* const* d_in, const int* in_sizes, int n_in,
                              void* d_out, int out_size)
{
    const float* hist  = (const float*)d_in[0];
    const float* eWih0 = (const float*)d_in[1];
    const float* eWhh0 = (const float*)d_in[2];
    const float* ebih0 = (const float*)d_in[3];
    const float* ebhh0 = (const float*)d_in[4];
    const float* eWih1 = (const float*)d_in[5];
    const float* eWhh1 = (const float*)d_in[6];
    const float* ebih1 = (const float*)d_in[7];
    const float* ebhh1 = (const float*)d_in[8];
    const float* dWih0 = (const float*)d_in[9];
    const float* dWhh0 = (const float*)d_in[10];
    const float* dbih0 = (const float*)d_in[11];
    const float* dbhh0 = (const float*)d_in[12];
    const float* dWih1 = (const float*)d_in[13];
    const float* dWhh1 = (const float*)d_in[14];
    const float* dbih1 = (const float*)d_in[15];
    const float* dbhh1 = (const float*)d_in[16];
    const float* headW = (const float*)d_in[17];
    const float* headb = (const float*)d_in[18];
    // d_in[19] = fut_len (always 30 for this problem)

    int B = in_sizes[0] / (T_HIST * FIN);
    int grid = B / ROWS;

    cudaFuncSetAttribute(lstm_forecaster_kernel,
                         cudaFuncAttributeMaxDynamicSharedMemorySize, SMEM_BYTES);

    lstm_forecaster_kernel<<<grid, THREADS, SMEM_BYTES>>>(
        hist, eWih0, eWhh0, ebih0, ebhh0, eWih1, eWhh1, ebih1, ebhh1,
        dWih0, dWhh0, dbih0, dbhh0, dWih1, dWhh1, dbih1, dbhh1,
        headW, headb, (float*)d_out);
}